// round 8
// baseline (speedup 1.0000x reference)
#include <cuda_runtime.h>
#include <math.h>

// Problem constants
#define XD 8            // feature dims (XD == ZD == 8)
#define LCH 64          // t-chunk length

// Scratch: per-chunk scan summaries U[c][r]
__device__ float g_U[64 * 8192];

// ---------------- packed fp32x2 helpers (sm_100a) ----------------
static __device__ __forceinline__ float2 ffma2(float2 a, float2 b, float2 c) {
    float2 d;
    asm("{\n\t"
        ".reg .b64 ra, rb, rc, rd;\n\t"
        "mov.b64 ra, {%2, %3};\n\t"
        "mov.b64 rb, {%4, %5};\n\t"
        "mov.b64 rc, {%6, %7};\n\t"
        "fma.rn.f32x2 rd, ra, rb, rc;\n\t"
        "mov.b64 {%0, %1}, rd;\n\t"
        "}"
        : "=f"(d.x), "=f"(d.y)
        : "f"(a.x), "f"(a.y), "f"(b.x), "f"(b.y), "f"(c.x), "f"(c.y));
    return d;
}

static __device__ __forceinline__ float2 fmul2(float2 a, float2 b) {
    float2 d;
    asm("{\n\t"
        ".reg .b64 ra, rb, rd;\n\t"
        "mov.b64 ra, {%2, %3};\n\t"
        "mov.b64 rb, {%4, %5};\n\t"
        "mul.rn.f32x2 rd, ra, rb;\n\t"
        "mov.b64 {%0, %1}, rd;\n\t"
        "}"
        : "=f"(d.x), "=f"(d.y)
        : "f"(a.x), "f"(a.y), "f"(b.x), "f"(b.y));
    return d;
}

static __device__ __forceinline__ float2 fadd2(float2 a, float2 b) {
    float2 d;
    asm("{\n\t"
        ".reg .b64 ra, rb, rd;\n\t"
        "mov.b64 ra, {%2, %3};\n\t"
        "mov.b64 rb, {%4, %5};\n\t"
        "add.rn.f32x2 rd, ra, rb;\n\t"
        "mov.b64 {%0, %1}, rd;\n\t"
        "}"
        : "=f"(d.x), "=f"(d.y)
        : "f"(a.x), "f"(a.y), "f"(b.x), "f"(b.y));
    return d;
}

static __device__ __forceinline__ float2 splat(float v) { return make_float2(v, v); }

static __device__ __forceinline__ float sigmoidf_(float x) {
    return 1.0f / (1.0f + expf(-x));
}

// Load coefficient row-pair {rA, rB} packed into float2[8]  (K1 only)
static __device__ __forceinline__ void load_pair(const float* __restrict__ base,
                                                 int rA, int rB, float2 o[XD]) {
    const float4 a0 = *(const float4*)(base + rA * XD);
    const float4 a1 = *(const float4*)(base + rA * XD + 4);
    const float4 b0 = *(const float4*)(base + rB * XD);
    const float4 b1 = *(const float4*)(base + rB * XD + 4);
    o[0] = make_float2(a0.x, b0.x); o[1] = make_float2(a0.y, b0.y);
    o[2] = make_float2(a0.z, b0.z); o[3] = make_float2(a0.w, b0.w);
    o[4] = make_float2(a1.x, b1.x); o[5] = make_float2(a1.y, b1.y);
    o[6] = make_float2(a1.z, b1.z); o[7] = make_float2(a1.w, b1.w);
}

static __device__ __forceinline__ float2 compute_b(const float2 ga[XD],
                                                   float4 z0, float4 z1) {
    float2 b0 = fmul2(ga[0], splat(z0.x));
    b0 = ffma2(ga[1], splat(z0.y), b0);
    b0 = ffma2(ga[2], splat(z0.z), b0);
    b0 = ffma2(ga[3], splat(z0.w), b0);
    float2 b1 = fmul2(ga[4], splat(z1.x));
    b1 = ffma2(ga[5], splat(z1.y), b1);
    b1 = ffma2(ga[6], splat(z1.z), b1);
    b1 = ffma2(ga[7], splat(z1.w), b1);
    return fadd2(b0, b1);
}

// ---------------- Kernel 1 (proven): per-chunk scan summaries ----------------
__global__ __launch_bounds__(128) void dlm_chunk_kernel(
    const float* __restrict__ Z, const float* __restrict__ G,
    const float* __restrict__ gamma, int R)
{
    __shared__ __align__(16) float sZ[LCH * XD];
    const int c = blockIdx.y;
    const int t0 = c * LCH;
    for (int i = threadIdx.x; i < LCH * XD; i += blockDim.x)
        sZ[i] = Z[t0 * XD + i];
    __syncthreads();

    const int warp = threadIdx.x >> 5, lane = threadIdx.x & 31;
    const int rbase = blockIdx.x * 256 + warp * 64;
    const int rA = rbase + lane, rB = rA + 32;

    float2 ga[XD];
    load_pair(gamma, rA, rB, ga);
    const float2 g2 = make_float2(sigmoidf_(G[rA]), sigmoidf_(G[rB]));

    float2 u = make_float2(0.f, 0.f);
#pragma unroll 4
    for (int i = 0; i < LCH; ++i) {
        const float4 z0 = *(const float4*)&sZ[i * XD];
        const float4 z1 = *(const float4*)&sZ[i * XD + 4];
        const float2 b = compute_b(ga, z0, z1);
        u = ffma2(g2, u, b);
    }
    g_U[c * R + rA] = u.x;
    g_U[c * R + rB] = u.y;
}

// ---------------- Kernel 2: t-packed f32x2, TWO rows per lane ----------------
// 16 LDS.128 per 4t are shared by both rows' fma chains (halves L1 per fma).
__global__ __launch_bounds__(128) void dlm_main_kernel(
    const float* __restrict__ X, const float* __restrict__ Z,
    const float* __restrict__ G, const float* __restrict__ eta,
    const float* __restrict__ zeta, const float* __restrict__ gamma,
    float* __restrict__ out, int R, int T)
{
    __shared__ __align__(16) float sXT[XD * 68];   // transposed: [d][t], stride 68
    __shared__ __align__(16) float sZT[XD * 68];
    __shared__ float tile[4][32 * 65];             // per warp: [t_local][row 0..63], stride 65

    const int c = blockIdx.y;
    const int t0 = c * LCH;
    for (int i = threadIdx.x; i < LCH * XD; i += blockDim.x) {
        const int t = i >> 3, d = i & 7;
        sXT[d * 68 + t] = X[t0 * XD + i];
        sZT[d * 68 + t] = Z[t0 * XD + i];
    }
    __syncthreads();

    const int warp = threadIdx.x >> 5, lane = threadIdx.x & 31;
    const int rwbase = blockIdx.x * 256 + warp * 64;
    const int rA = rwbase + lane, rB = rA + 32;   // two rows per lane

    // Hoisted coefficient splats for both rows (loop-invariant)
    float2 etA[XD], zeA[XD], gaA[XD], etB[XD], zeB[XD], gaB[XD];
    {
        const float4 a0 = *(const float4*)(eta + rA * XD);
        const float4 a1 = *(const float4*)(eta + rA * XD + 4);
        etA[0]=splat(a0.x); etA[1]=splat(a0.y); etA[2]=splat(a0.z); etA[3]=splat(a0.w);
        etA[4]=splat(a1.x); etA[5]=splat(a1.y); etA[6]=splat(a1.z); etA[7]=splat(a1.w);
        const float4 b0 = *(const float4*)(eta + rB * XD);
        const float4 b1 = *(const float4*)(eta + rB * XD + 4);
        etB[0]=splat(b0.x); etB[1]=splat(b0.y); etB[2]=splat(b0.z); etB[3]=splat(b0.w);
        etB[4]=splat(b1.x); etB[5]=splat(b1.y); etB[6]=splat(b1.z); etB[7]=splat(b1.w);
    }
    {
        const float4 a0 = *(const float4*)(zeta + rA * XD);
        const float4 a1 = *(const float4*)(zeta + rA * XD + 4);
        zeA[0]=splat(a0.x); zeA[1]=splat(a0.y); zeA[2]=splat(a0.z); zeA[3]=splat(a0.w);
        zeA[4]=splat(a1.x); zeA[5]=splat(a1.y); zeA[6]=splat(a1.z); zeA[7]=splat(a1.w);
        const float4 b0 = *(const float4*)(zeta + rB * XD);
        const float4 b1 = *(const float4*)(zeta + rB * XD + 4);
        zeB[0]=splat(b0.x); zeB[1]=splat(b0.y); zeB[2]=splat(b0.z); zeB[3]=splat(b0.w);
        zeB[4]=splat(b1.x); zeB[5]=splat(b1.y); zeB[6]=splat(b1.z); zeB[7]=splat(b1.w);
    }
    {
        const float4 a0 = *(const float4*)(gamma + rA * XD);
        const float4 a1 = *(const float4*)(gamma + rA * XD + 4);
        gaA[0]=splat(a0.x); gaA[1]=splat(a0.y); gaA[2]=splat(a0.z); gaA[3]=splat(a0.w);
        gaA[4]=splat(a1.x); gaA[5]=splat(a1.y); gaA[6]=splat(a1.z); gaA[7]=splat(a1.w);
        const float4 b0 = *(const float4*)(gamma + rB * XD);
        const float4 b1 = *(const float4*)(gamma + rB * XD + 4);
        gaB[0]=splat(b0.x); gaB[1]=splat(b0.y); gaB[2]=splat(b0.z); gaB[3]=splat(b0.w);
        gaB[4]=splat(b1.x); gaB[5]=splat(b1.y); gaB[6]=splat(b1.z); gaB[7]=splat(b1.w);
    }

    const float gA = sigmoidf_(G[rA]);
    const float gB = sigmoidf_(G[rB]);
    float glA = gA, glB = gB;
#pragma unroll
    for (int s = 0; s < 6; ++s) { glA = glA * glA; glB = glB * glB; }   // Ghat^64

    // Carry-in: prefix over previous chunks' summaries (two independent chains)
    float thA = 0.f, thB = 0.f;
#pragma unroll 4
    for (int j = 0; j < c; ++j) {
        thA = fmaf(glA, thA, __ldg(&g_U[j * R + rA]));
        thB = fmaf(glB, thB, __ldg(&g_U[j * R + rB]));
    }

    float* mytile = tile[warp];
#pragma unroll
    for (int tb = 0; tb < 2; ++tb) {
#pragma unroll 2
        for (int i = 0; i < 8; ++i) {
            const int tl = tb * 32 + i * 4;        // 4 time steps this iter

            // ---- shared data loads: 16 x LDS.128, feed BOTH rows ----
            float4 xv[XD], zv[XD];
#pragma unroll
            for (int d = 0; d < XD; ++d) xv[d] = *(const float4*)&sXT[d * 68 + tl];
#pragma unroll
            for (int d = 0; d < XD; ++d) zv[d] = *(const float4*)&sZT[d * 68 + tl];

            // ---- row A chains ----
            float2 A01a = fmul2(etA[0], make_float2(xv[0].x, xv[0].y));
            float2 A23a = fmul2(etA[0], make_float2(xv[0].z, xv[0].w));
            float2 A01b = fmul2(etB[0], make_float2(xv[0].x, xv[0].y));
            float2 A23b = fmul2(etB[0], make_float2(xv[0].z, xv[0].w));
#pragma unroll
            for (int d = 1; d < XD; ++d) {
                const float2 x01 = make_float2(xv[d].x, xv[d].y);
                const float2 x23 = make_float2(xv[d].z, xv[d].w);
                A01a = ffma2(etA[d], x01, A01a);
                A23a = ffma2(etA[d], x23, A23a);
                A01b = ffma2(etB[d], x01, A01b);
                A23b = ffma2(etB[d], x23, A23b);
            }

            // ---- zeta & gamma chains for both rows (share zv) ----
            float2 B01a, B23a, b01a, b23a, B01b, B23b, b01b, b23b;
#pragma unroll
            for (int d = 0; d < XD; ++d) {
                const float2 z01 = make_float2(zv[d].x, zv[d].y);
                const float2 z23 = make_float2(zv[d].z, zv[d].w);
                if (d == 0) {
                    B01a = fmul2(zeA[0], z01); B23a = fmul2(zeA[0], z23);
                    b01a = fmul2(gaA[0], z01); b23a = fmul2(gaA[0], z23);
                    B01b = fmul2(zeB[0], z01); B23b = fmul2(zeB[0], z23);
                    b01b = fmul2(gaB[0], z01); b23b = fmul2(gaB[0], z23);
                } else {
                    B01a = ffma2(zeA[d], z01, B01a); B23a = ffma2(zeA[d], z23, B23a);
                    b01a = ffma2(gaA[d], z01, b01a); b23a = ffma2(gaA[d], z23, b23a);
                    B01b = ffma2(zeB[d], z01, B01b); B23b = ffma2(zeB[d], z23, B23b);
                    b01b = ffma2(gaB[d], z01, b01b); b23b = ffma2(gaB[d], z23, b23b);
                }
            }
            const float2 xz01a = fadd2(A01a, B01a), xz23a = fadd2(A23a, B23a);
            const float2 xz01b = fadd2(A01b, B01b), xz23b = fadd2(A23b, B23b);

            // Scalar recurrence + output assembly, both rows (independent chains)
            const float oa0 = thA + xz01a.x;  thA = fmaf(gA, thA, b01a.x);
            const float ob0 = thB + xz01b.x;  thB = fmaf(gB, thB, b01b.x);
            const float oa1 = thA + xz01a.y;  thA = fmaf(gA, thA, b01a.y);
            const float ob1 = thB + xz01b.y;  thB = fmaf(gB, thB, b01b.y);
            const float oa2 = thA + xz23a.x;  thA = fmaf(gA, thA, b23a.x);
            const float ob2 = thB + xz23b.x;  thB = fmaf(gB, thB, b23b.x);
            const float oa3 = thA + xz23a.y;  thA = fmaf(gA, thA, b23a.y);
            const float ob3 = thB + xz23b.y;  thB = fmaf(gB, thB, b23b.y);

            const int tt = i * 4;                  // local t within tile
            mytile[(tt + 0) * 65 + lane]      = oa0;   // bank t+lane: conflict-free
            mytile[(tt + 1) * 65 + lane]      = oa1;
            mytile[(tt + 2) * 65 + lane]      = oa2;
            mytile[(tt + 3) * 65 + lane]      = oa3;
            mytile[(tt + 0) * 65 + lane + 32] = ob0;
            mytile[(tt + 1) * 65 + lane + 32] = ob1;
            mytile[(tt + 2) * 65 + lane + 32] = ob2;
            mytile[(tt + 3) * 65 + lane + 32] = ob3;
        }
        __syncwarp();
        // Coalesced writeback: 16 x STG.128; transpose reads bank-bijective
        // (bank = 4*(lane&7) + (lane>>3) + const, covers 0..31 once per LDS)
        const int tbase = t0 + tb * 32;
#pragma unroll
        for (int k = 0; k < 16; ++k) {
            const int sid = k * 32 + lane;
            const int row = sid >> 3;              // 0..63
            const int tg  = (sid & 7) << 2;        // 0,4,...,28
            float4 v;
            v.x = mytile[(tg + 0) * 65 + row];
            v.y = mytile[(tg + 1) * 65 + row];
            v.z = mytile[(tg + 2) * 65 + row];
            v.w = mytile[(tg + 3) * 65 + row];
            *(float4*)&out[(rwbase + row) * T + tbase + tg] = v;
        }
        __syncwarp();
    }
}

// ---------------- launch ----------------
extern "C" void kernel_launch(void* const* d_in, const int* in_sizes, int n_in,
                              void* d_out, int out_size) {
    const float* X     = (const float*)d_in[0];   // [T, 8]
    const float* Z     = (const float*)d_in[1];   // [T, 8]
    const float* G     = (const float*)d_in[2];   // [R]
    const float* eta   = (const float*)d_in[3];   // [R, 8]
    const float* zeta  = (const float*)d_in[4];   // [R, 8]
    const float* gamma = (const float*)d_in[5];   // [R, 8]
    float* out = (float*)d_out;                   // [R, T]

    const int T = in_sizes[0] / XD;   // 2048
    const int R = in_sizes[2];        // 4096
    const int NC = T / LCH;           // 32 chunks

    // K1: chunk summaries (proven shape). grid (16, 32), 128 threads.
    dlm_chunk_kernel<<<dim3(R / 256, NC), 128>>>(Z, G, gamma, R);
    // K2: main, t-packed, 2 rows/lane. grid (16, 32) = 512 CTAs, 128 threads.
    dlm_main_kernel<<<dim3(R / 256, NC), 128>>>(X, Z, G, eta, zeta, gamma, out, R, T);
}